// round 6
// baseline (speedup 1.0000x reference)
#include <cuda_runtime.h>
#include <cstdint>

#define BB 8
#define ANCH 22743
#define PRE 400
#define NCAND 4096

typedef unsigned long long u64;

static __device__ float g_x[46208 * 256];
static __device__ float g_pred[46208 * 255];
static __device__ float g_boxes[BB * ANCH * 4];
static __device__ float g_scores[BB * ANCH * 80];
static __device__ unsigned g_h16[BB * 65536];
static __device__ unsigned g_p16[BB];
static __device__ int g_candn[BB];
static __device__ unsigned long long g_ckey[BB * NCAND];
static __device__ float g_tops[BB * PRE];
static __device__ int g_topi[BB * PRE];

__constant__ float c_anch[9][2] = {{12,16},{19,36},{40,28},{36,75},{76,55},
                                   {72,146},{142,110},{192,243},{459,401}};

__device__ __forceinline__ float fdiv_rn(float a, float b) {
    float r; asm("div.rn.f32 %0,%1,%2;" : "=f"(r) : "f"(a), "f"(b)); return r;
}
__device__ __forceinline__ float exp_f(float x) {
    float n = rintf(x * 1.4426950408889634f);
    float r = fmaf(n, -0.693359375f, x);
    r = fmaf(n, 2.12194440e-4f, r);
    float p = 1.98412698e-4f;
    p = fmaf(p, r, 1.38888889e-3f);
    p = fmaf(p, r, 8.33333333e-3f);
    p = fmaf(p, r, 4.16666667e-2f);
    p = fmaf(p, r, 0.166666667f);
    p = fmaf(p, r, 0.5f);
    p = fmaf(p, r, 1.0f);
    p = fmaf(p, r, 1.0f);
    int ni = (int)n; ni = ni < -126 ? -126 : (ni > 127 ? 127 : ni);
    return p * __int_as_float((ni + 127) << 23);
}
__device__ __forceinline__ float sigmoid_f(float x) {
    return fdiv_rn(1.0f, 1.0f + exp_f(-x));
}

__device__ __forceinline__ u64 pack2(float lo, float hi) {
    u64 r; asm("mov.b64 %0,{%1,%2};" : "=l"(r) : "f"(lo), "f"(hi)); return r;
}
__device__ __forceinline__ void unpack2(u64 v, float& lo, float& hi) {
    asm("mov.b64 {%0,%1},%2;" : "=f"(lo), "=f"(hi) : "l"(v));
}
__device__ __forceinline__ u64 ffma2(u64 a, u64 b, u64 c) {
    u64 d; asm("fma.rn.f32x2 %0,%1,%2,%3;" : "=l"(d) : "l"(a), "l"(b), "l"(c)); return d;
}

// ---------------- 128x128x8 double-buffered SGEMM, f32x2 inner loop ----------------
// MODE 0: 3x3 implicit-GEMM conv + BN + leaky.  MODE 1: 1x1 conv + bias (N=255).
template<int MODE, int VECB>
__global__ void __launch_bounds__(256) gemm2_kernel(
    const float* __restrict__ A, const float* __restrict__ Bw,
    const float* __restrict__ p0, const float* __restrict__ p1,
    float* __restrict__ out, int M, int N, int K, int Himg, int Cin, int cshift)
{
    __shared__ __align__(16) float As[2][8][132];
    __shared__ __align__(16) float Bs[2][8][132];
    const int t = threadIdx.x;
    const int m0 = blockIdx.y * 128;
    const int bn = blockIdx.x * 128;
    const int tx = t & 15, ty = t >> 4;

    const int am = t >> 1, kq = (t & 1) * 4;
    const int gm = m0 + am;
    const bool mval = gm < M;
    int nImg = 0, y = 0, x = 0;
    if (MODE == 0) {
        int hw = Himg * Himg;
        int gg = mval ? gm : 0;
        nImg = gg / hw; int rr = gg - nImg * hw; y = rr / Himg; x = rr - y * Himg;
    }
    const int bk = t >> 5, bn0 = (t & 31) * 4;
    const int gn = bn + bn0;

    u64 acc2[8][4];
    #pragma unroll
    for (int i = 0; i < 8; i++)
        #pragma unroll
        for (int j = 0; j < 4; j++) acc2[i][j] = 0ull;

    const int nt = K >> 3;
    float4 pa = make_float4(0.f, 0.f, 0.f, 0.f);
    float4 pb = make_float4(0.f, 0.f, 0.f, 0.f);

    {   // prologue (tile 0)
        if (MODE == 0) {
            bool v = mval && ((unsigned)(y - 1) < (unsigned)Himg) &&
                     ((unsigned)(x - 1) < (unsigned)Himg);
            if (v) pa = *(const float4*)(A + (((size_t)nImg * Himg + (y - 1)) * Himg + (x - 1)) * Cin + kq);
        } else if (mval) {
            pa = *(const float4*)(A + (size_t)gm * K + kq);
        }
        const float* s = Bw + (size_t)bk * N + gn;
        if (VECB) { if (gn < N) pb = *(const float4*)s; }
        else {
            if (gn + 3 < N) { pb.x = s[0]; pb.y = s[1]; pb.z = s[2]; pb.w = s[3]; }
            else { if (gn < N) pb.x = s[0]; if (gn + 1 < N) pb.y = s[1]; if (gn + 2 < N) pb.z = s[2]; }
        }
    }
    As[0][kq + 0][am] = pa.x; As[0][kq + 1][am] = pa.y;
    As[0][kq + 2][am] = pa.z; As[0][kq + 3][am] = pa.w;
    *(float4*)&Bs[0][bk][bn0] = pb;
    __syncthreads();

    int cur = 0;
    for (int kt = 0; kt < nt; kt++) {
        const bool more = (kt + 1) < nt;
        if (more) {
            const int k0 = (kt + 1) << 3;
            pa = make_float4(0.f, 0.f, 0.f, 0.f);
            pb = make_float4(0.f, 0.f, 0.f, 0.f);
            if (MODE == 0) {
                int win = k0 >> cshift;
                int ky = win / 3, kx = win - ky * 3;
                int yy = y + ky - 1, xx = x + kx - 1;
                bool v = mval && ((unsigned)yy < (unsigned)Himg) && ((unsigned)xx < (unsigned)Himg);
                if (v) pa = *(const float4*)(A + (((size_t)nImg * Himg + yy) * Himg + xx) * Cin
                                               + (k0 & (Cin - 1)) + kq);
            } else if (mval) {
                pa = *(const float4*)(A + (size_t)gm * K + k0 + kq);
            }
            const float* s = Bw + (size_t)(k0 + bk) * N + gn;
            if (VECB) { if (gn < N) pb = *(const float4*)s; }
            else {
                if (gn + 3 < N) { pb.x = s[0]; pb.y = s[1]; pb.z = s[2]; pb.w = s[3]; }
                else { if (gn < N) pb.x = s[0]; if (gn + 1 < N) pb.y = s[1]; if (gn + 2 < N) pb.z = s[2]; }
            }
        }
        #pragma unroll
        for (int kk = 0; kk < 8; kk++) {
            float4 a0 = *(const float4*)&As[cur][kk][ty * 8];
            float4 a1 = *(const float4*)&As[cur][kk][ty * 8 + 4];
            float4 b0 = *(const float4*)&Bs[cur][kk][tx * 8];
            float4 b1 = *(const float4*)&Bs[cur][kk][tx * 8 + 4];
            u64 bp0 = pack2(b0.x, b0.y), bp1 = pack2(b0.z, b0.w);
            u64 bp2 = pack2(b1.x, b1.y), bp3 = pack2(b1.z, b1.w);
            float av[8] = {a0.x, a0.y, a0.z, a0.w, a1.x, a1.y, a1.z, a1.w};
            #pragma unroll
            for (int i = 0; i < 8; i++) {
                u64 ad = pack2(av[i], av[i]);
                acc2[i][0] = ffma2(ad, bp0, acc2[i][0]);
                acc2[i][1] = ffma2(ad, bp1, acc2[i][1]);
                acc2[i][2] = ffma2(ad, bp2, acc2[i][2]);
                acc2[i][3] = ffma2(ad, bp3, acc2[i][3]);
            }
        }
        if (more) {
            int nb = cur ^ 1;
            As[nb][kq + 0][am] = pa.x; As[nb][kq + 1][am] = pa.y;
            As[nb][kq + 2][am] = pa.z; As[nb][kq + 3][am] = pa.w;
            *(float4*)&Bs[nb][bk][bn0] = pb;
            __syncthreads();
            cur = nb;
        }
    }

    if (MODE == 0) {
        float gg[8], bb[8];
        #pragma unroll
        for (int j = 0; j < 8; j++) {
            int nn = bn + tx * 8 + j;
            gg[j] = p0[nn]; bb[j] = p1[nn];
        }
        #pragma unroll
        for (int i = 0; i < 8; i++) {
            int mm = m0 + ty * 8 + i;
            if (mm >= M) continue;
            float a[8];
            unpack2(acc2[i][0], a[0], a[1]); unpack2(acc2[i][1], a[2], a[3]);
            unpack2(acc2[i][2], a[4], a[5]); unpack2(acc2[i][3], a[6], a[7]);
            float* o = out + (size_t)mm * N + bn + tx * 8;
            float4 v0, v1;
            float w0 = fmaf(a[0], gg[0], bb[0]); v0.x = w0 > 0.f ? w0 : 0.1f * w0;
            float w1 = fmaf(a[1], gg[1], bb[1]); v0.y = w1 > 0.f ? w1 : 0.1f * w1;
            float w2 = fmaf(a[2], gg[2], bb[2]); v0.z = w2 > 0.f ? w2 : 0.1f * w2;
            float w3 = fmaf(a[3], gg[3], bb[3]); v0.w = w3 > 0.f ? w3 : 0.1f * w3;
            float w4 = fmaf(a[4], gg[4], bb[4]); v1.x = w4 > 0.f ? w4 : 0.1f * w4;
            float w5 = fmaf(a[5], gg[5], bb[5]); v1.y = w5 > 0.f ? w5 : 0.1f * w5;
            float w6 = fmaf(a[6], gg[6], bb[6]); v1.z = w6 > 0.f ? w6 : 0.1f * w6;
            float w7 = fmaf(a[7], gg[7], bb[7]); v1.w = w7 > 0.f ? w7 : 0.1f * w7;
            *(float4*)o = v0;
            *(float4*)(o + 4) = v1;
        }
    } else {
        #pragma unroll
        for (int i = 0; i < 8; i++) {
            int mm = m0 + ty * 8 + i;
            if (mm >= M) continue;
            float a[8];
            unpack2(acc2[i][0], a[0], a[1]); unpack2(acc2[i][1], a[2], a[3]);
            unpack2(acc2[i][2], a[4], a[5]); unpack2(acc2[i][3], a[6], a[7]);
            #pragma unroll
            for (int j = 0; j < 8; j++) {
                int nn = bn + tx * 8 + j;
                if (nn < N) out[(size_t)mm * N + nn] = a[j] + p1[nn];
            }
        }
    }
}

__global__ void decode_kernel(const float* __restrict__ pred, int Hl, int lvloff,
                              int abase, float stride)
{
    int idx = blockIdx.x * blockDim.x + threadIdx.x;
    int total = BB * Hl * Hl * 3;
    if (idx >= total) return;
    int a = idx % 3;
    int r = idx / 3;
    int hw = Hl * Hl;
    int b = r / hw;
    int cell = r - b * hw;
    int y = cell / Hl, x = cell - y * Hl;
    const float* p = pred + (size_t)r * 255 + a * 85;
    float cx = (fmaf(sigmoid_f(p[0]), 1.05f, -0.025f) + (float)x) * stride;
    float cy = (fmaf(sigmoid_f(p[1]), 1.05f, -0.025f) + (float)y) * stride;
    float w = exp_f(p[2]) * c_anch[abase + a][0];
    float h = exp_f(p[3]) * c_anch[abase + a][1];
    int g = lvloff + cell * 3 + a;
    float* bx = g_boxes + ((size_t)b * ANCH + g) * 4;
    bx[0] = cx - 0.5f * w; bx[1] = cy - 0.5f * h;
    bx[2] = cx + 0.5f * w; bx[3] = cy + 0.5f * h;
    float sobj = sigmoid_f(p[4]);
    float* sc = g_scores + ((size_t)b * ANCH + g) * 80;
    #pragma unroll 4
    for (int c = 0; c < 80; c++) sc[c] = sobj * sigmoid_f(p[5 + c]);
}

__global__ void zero_kernel() {
    int i = blockIdx.x * blockDim.x + threadIdx.x;
    if (i < BB * 65536) g_h16[i] = 0u;
    if (i < BB) { g_candn[i] = 0; g_p16[i] = 0u; }
}

// 16-bit-prefix histogram; smem ushort-pair counters (128KB dynamic).
// grid (32, BB): per-block item count 56858 < 65536 -> no ushort overflow.
__global__ void __launch_bounds__(256) hist16_kernel() {
    extern __shared__ unsigned shw[];          // 32768 words = 65536 ushort bins
    const int b = blockIdx.y;
    for (int i = threadIdx.x; i < 32768; i += 256) shw[i] = 0u;
    __syncthreads();
    const float* s = g_scores + (size_t)b * (ANCH * 80);
    const int n = ANCH * 80;
    const int stride = 256 * gridDim.x;
    for (int i = blockIdx.x * 256 + threadIdx.x; i < n; i += stride) {
        float v = s[i];
        if (v >= 0.05f) {
            unsigned bin = __float_as_uint(v) >> 16;
            unsigned act = __activemask();
            unsigned mm = __match_any_sync(act, bin);
            if ((threadIdx.x & 31) == __ffs(mm) - 1)
                atomicAdd(&shw[bin >> 1], (unsigned)__popc(mm) << ((bin & 1) * 16));
        }
    }
    __syncthreads();
    for (int i = threadIdx.x; i < 32768; i += 256) {
        unsigned w = shw[i];
        if (w) {
            unsigned lo = w & 0xFFFFu, hi = w >> 16;
            if (lo) atomicAdd(&g_h16[b * 65536 + 2 * i], lo);
            if (hi) atomicAdd(&g_h16[b * 65536 + 2 * i + 1], hi);
        }
    }
}

__global__ void select16_kernel() {
    __shared__ unsigned part[256];
    const int b = blockIdx.x, t = threadIdx.x;
    const unsigned* h = g_h16 + b * 65536;
    const int hi = 65536 - 256 * t;
    const int lo = hi - 256;
    unsigned sum = 0;
    for (int i = lo; i < hi; i++) sum += h[i];
    part[t] = sum;
    __syncthreads();
    unsigned pre = 0;
    for (int i = 0; i < t; i++) pre += part[i];
    if (pre < PRE) {
        unsigned cum = pre;
        for (int i = hi - 1; i >= lo; i--) {
            unsigned c = h[i];
            if (cum < PRE && cum + c >= PRE) g_p16[b] = (unsigned)i;
            cum += c;
        }
    }
}

__global__ void compact_kernel() {
    const int b = blockIdx.y;
    const unsigned p16 = g_p16[b];
    const float* s = g_scores + (size_t)b * (ANCH * 80);
    const int n = ANCH * 80;
    const int stride = blockDim.x * gridDim.x;
    for (int i = blockIdx.x * blockDim.x + threadIdx.x; i < n; i += stride) {
        float v = s[i];
        if (v >= 0.05f) {
            unsigned bits = __float_as_uint(v);
            if ((bits >> 16) >= p16) {
                int pos = atomicAdd(&g_candn[b], 1);
                if (pos < NCAND)
                    g_ckey[b * NCAND + pos] =
                        ((unsigned long long)(~bits) << 32) | (unsigned)i;
            }
        }
    }
}

__device__ void bitonic(unsigned long long* keys, int n) {
    const int t = threadIdx.x, nt = blockDim.x;
    for (int k = 2; k <= n; k <<= 1)
        for (int j = k >> 1; j > 0; j >>= 1) {
            for (int i = t; i < n; i += nt) {
                int ixj = i ^ j;
                if (ixj > i) {
                    unsigned long long a = keys[i], c = keys[ixj];
                    bool sw = ((i & k) == 0) ? (a > c) : (a < c);
                    if (sw) { keys[i] = c; keys[ixj] = a; }
                }
            }
            __syncthreads();
        }
}

__global__ void __launch_bounds__(256) sortcand_kernel() {
    __shared__ unsigned long long keys[NCAND];
    const int b = blockIdx.x, t = threadIdx.x;
    int n = g_candn[b]; if (n > NCAND) n = NCAND;
    for (int i = t; i < NCAND; i += blockDim.x)
        keys[i] = (i < n) ? g_ckey[b * NCAND + i] : 0xFFFFFFFFFFFFFFFFull;
    __syncthreads();
    bitonic(keys, NCAND);
    for (int i = t; i < PRE; i += blockDim.x) {
        if (i < n) {
            unsigned long long k = keys[i];
            g_topi[b * PRE + i] = (int)(unsigned)(k & 0xffffffffu);
            g_tops[b * PRE + i] = __uint_as_float(~(unsigned)(k >> 32));
        } else {
            g_topi[b * PRE + i] = 0;
            g_tops[b * PRE + i] = 0.f;
        }
    }
}

__global__ void __launch_bounds__(256) nms_kernel(float* __restrict__ dout) {
    __shared__ float x1s[PRE], y1s[PRE], x2s[PRE], y2s[PRE];
    __shared__ float rbx[PRE][4];
    __shared__ float ar[PRE], sc[PRE];
    __shared__ int cls[PRE];
    __shared__ unsigned sup[PRE][13];
    __shared__ unsigned keepw[13];
    __shared__ unsigned long long keys[512];
    const int b = blockIdx.x, t = threadIdx.x;
    for (int i = t; i < PRE; i += 256) {
        float s = g_tops[b * PRE + i];
        int fi = g_topi[b * PRE + i];
        int aidx = fi / 80;
        int c = fi - aidx * 80;
        const float* bx = g_boxes + ((size_t)b * ANCH + aidx) * 4;
        float off = (float)c * 1216.0f;
        float X1 = bx[0], Y1 = bx[1], X2 = bx[2], Y2 = bx[3];
        rbx[i][0] = X1; rbx[i][1] = Y1; rbx[i][2] = X2; rbx[i][3] = Y2;
        x1s[i] = X1 + off; y1s[i] = Y1 + off;
        x2s[i] = X2 + off; y2s[i] = Y2 + off;
        ar[i] = (X2 - X1) * (Y2 - Y1);
        sc[i] = s; cls[i] = c;
    }
    if (t < 13) keepw[t] = 0xFFFFFFFFu;
    __syncthreads();
    for (int i = t; i < PRE; i += 256) {
        float ax1 = x1s[i], ay1 = y1s[i], ax2 = x2s[i], ay2 = y2s[i], aa = ar[i];
        unsigned row[13];
        #pragma unroll
        for (int w = 0; w < 13; w++) row[w] = 0u;
        for (int j = i + 1; j < PRE; j++) {
            float ltx = fmaxf(ax1, x1s[j]), lty = fmaxf(ay1, y1s[j]);
            float rbxv = fminf(ax2, x2s[j]), rby = fminf(ay2, y2s[j]);
            float iw = fmaxf(rbxv - ltx, 0.f), ih = fmaxf(rby - lty, 0.f);
            float inter = iw * ih;
            float iou = fdiv_rn(inter, aa + ar[j] - inter + 1e-7f);
            if (iou > 0.5f) row[j >> 5] |= 1u << (j & 31);
        }
        #pragma unroll
        for (int w = 0; w < 13; w++) sup[i][w] = row[w];
    }
    __syncthreads();
    if (t == 0) {
        for (int i = 0; i < PRE; i++)
            if (((keepw[i >> 5] >> (i & 31)) & 1u) && sc[i] > 0.f)
                for (int w = i >> 5; w < 13; w++) keepw[w] &= ~sup[i][w];
    }
    __syncthreads();
    for (int i = t; i < 512; i += 256) {
        if (i < PRE) {
            bool k = (keepw[i >> 5] >> (i & 31)) & 1u;
            float fs = k ? sc[i] : 0.f;
            keys[i] = ((unsigned long long)(~__float_as_uint(fs)) << 32) | (unsigned)i;
        } else keys[i] = 0xFFFFFFFFFFFFFFFFull;
    }
    __syncthreads();
    bitonic(keys, 512);
    for (int k = t; k < 100; k += 256) {
        unsigned long long key = keys[k];
        unsigned idx = (unsigned)(key & 0xffffffffu);
        float s = __uint_as_float(~(unsigned)(key >> 32));
        float o0 = 0, o1 = 0, o2 = 0, o3 = 0, cf = 0;
        if (idx < PRE) {
            o0 = rbx[idx][0]; o1 = rbx[idx][1]; o2 = rbx[idx][2]; o3 = rbx[idx][3];
            cf = (float)cls[idx];
        } else s = 0.f;
        float* ob = dout + ((size_t)b * 100 + k) * 4;
        ob[0] = o0; ob[1] = o1; ob[2] = o2; ob[3] = o3;
        dout[3200 + b * 100 + k] = s;
        dout[4000 + b * 100 + k] = cf;
    }
}

extern "C" void kernel_launch(void* const* d_in, const int* in_sizes, int n_in,
                              void* d_out, int out_size) {
    const float *f[3], *w3[3], *ga[3], *be[3], *w1[3], *b1[3];
    bool sig = (in_sizes[1] == 2957312);  // f1 in signature order
    for (int i = 0; i < 3; i++) {
        if (sig) {
            f[i]  = (const float*)d_in[i];
            w3[i] = (const float*)d_in[3 + 5 * i];
            ga[i] = (const float*)d_in[4 + 5 * i];
            be[i] = (const float*)d_in[5 + 5 * i];
            w1[i] = (const float*)d_in[6 + 5 * i];
            b1[i] = (const float*)d_in[7 + 5 * i];
        } else {
            int o = 6 * i;
            f[i]  = (const float*)d_in[o];
            w3[i] = (const float*)d_in[o + 1];
            ga[i] = (const float*)d_in[o + 2];
            be[i] = (const float*)d_in[o + 3];
            w1[i] = (const float*)d_in[o + 4];
            b1[i] = (const float*)d_in[o + 5];
        }
    }
    float *px = nullptr, *ppred = nullptr;
    cudaGetSymbolAddress((void**)&px, g_x);
    cudaGetSymbolAddress((void**)&ppred, g_pred);
    cudaFuncSetAttribute(hist16_kernel, cudaFuncAttributeMaxDynamicSharedMemorySize, 131072);

    static const int   Hs[3]    = {76, 38, 19};
    static const int   Cins[3]  = {128, 256, 512};
    static const int   CSH[3]   = {7, 8, 9};
    static const int   HDs[3]   = {256, 512, 1024};
    static const int   LOFF[3]  = {0, 17328, 21660};
    static const int   ABASE[3] = {0, 3, 6};
    static const float STR[3]   = {8.f, 16.f, 32.f};

    zero_kernel<<<(BB * 65536 + 255) / 256, 256>>>();

    for (int i = 0; i < 3; i++) {
        int H = Hs[i], Cin = Cins[i], hd = HDs[i];
        int M = BB * H * H;
        dim3 g1(hd / 128, (M + 127) / 128);
        gemm2_kernel<0, 1><<<g1, 256>>>(f[i], w3[i], ga[i], be[i], px,
                                        M, hd, 9 * Cin, H, Cin, CSH[i]);
        dim3 g2(2, (M + 127) / 128);
        gemm2_kernel<1, 0><<<g2, 256>>>(px, w1[i], b1[i], b1[i], ppred,
                                        M, 255, hd, 0, 0, 0);
        int tot = M * 3;
        decode_kernel<<<(tot + 255) / 256, 256>>>(ppred, H, LOFF[i], ABASE[i], STR[i]);
    }

    dim3 hg(32, BB);
    hist16_kernel<<<hg, 256, 131072>>>();
    select16_kernel<<<BB, 256>>>();
    compact_kernel<<<hg, 256>>>();
    sortcand_kernel<<<BB, 256>>>();
    nms_kernel<<<BB, 256>>>((float*)d_out);
}

// round 7
// speedup vs baseline: 1.0934x; 1.0934x over previous
#include <cuda_runtime.h>
#include <cstdint>

#define BB 8
#define ANCH 22743
#define PRE 400
#define NCAND 4096

static __device__ float g_x[46208 * 256];
static __device__ float g_pred[46208 * 255];
static __device__ float g_boxes[BB * ANCH * 4];
static __device__ float g_scores[BB * ANCH * 80];
static __device__ unsigned g_h16[BB * 65536];
static __device__ unsigned g_p16[BB];
static __device__ int g_candn[BB];
static __device__ unsigned long long g_ckey[BB * NCAND];
static __device__ float g_tops[BB * PRE];
static __device__ int g_topi[BB * PRE];

__constant__ float c_anch[9][2] = {{12,16},{19,36},{40,28},{36,75},{76,55},
                                   {72,146},{142,110},{192,243},{459,401}};

__device__ __forceinline__ float fdiv_rn(float a, float b) {
    float r; asm("div.rn.f32 %0,%1,%2;" : "=f"(r) : "f"(a), "f"(b)); return r;
}
__device__ __forceinline__ float exp_f(float x) {
    float n = rintf(x * 1.4426950408889634f);
    float r = fmaf(n, -0.693359375f, x);
    r = fmaf(n, 2.12194440e-4f, r);
    float p = 1.98412698e-4f;
    p = fmaf(p, r, 1.38888889e-3f);
    p = fmaf(p, r, 8.33333333e-3f);
    p = fmaf(p, r, 4.16666667e-2f);
    p = fmaf(p, r, 0.166666667f);
    p = fmaf(p, r, 0.5f);
    p = fmaf(p, r, 1.0f);
    p = fmaf(p, r, 1.0f);
    int ni = (int)n; ni = ni < -126 ? -126 : (ni > 127 ? 127 : ni);
    return p * __int_as_float((ni + 127) << 23);
}
__device__ __forceinline__ float sigmoid_f(float x) {
    return fdiv_rn(1.0f, 1.0f + exp_f(-x));
}

// ---------------- 128x128x16 double-buffered SGEMM, scalar FFMA ----------------
// MODE 0: 3x3 implicit-GEMM conv + BN + leaky.  MODE 1: 1x1 conv + bias (N=255).
template<int MODE, int VECB>
__global__ void __launch_bounds__(256) gemm2_kernel(
    const float* __restrict__ A, const float* __restrict__ Bw,
    const float* __restrict__ p0, const float* __restrict__ p1,
    float* __restrict__ out, int M, int N, int K, int Himg, int Cin, int cshift)
{
    __shared__ __align__(16) float As[2][16][132];
    __shared__ __align__(16) float Bs[2][16][132];
    const int t = threadIdx.x;
    const int m0 = blockIdx.y * 128;
    const int bn = blockIdx.x * 128;
    const int tx = t & 15, ty = t >> 4;

    // A loader: row am, 8 consecutive k at kq (2 float4)
    const int am = t >> 1, kq = (t & 1) * 8;
    const int gm = m0 + am;
    const bool mval = gm < M;
    int nImg = 0, y = 0, x = 0;
    if (MODE == 0) {
        int hw = Himg * Himg;
        int gg = mval ? gm : 0;
        nImg = gg / hw; int rr = gg - nImg * hw; y = rr / Himg; x = rr - y * Himg;
    }
    // B loader: rows bk and bk+8, 4 cols at bn0
    const int bk = t >> 5, bn0 = (t & 31) * 4;
    const int gn = bn + bn0;

    float acc[8][8];
    #pragma unroll
    for (int i = 0; i < 8; i++)
        #pragma unroll
        for (int j = 0; j < 8; j++) acc[i][j] = 0.f;

    const int nt = K >> 4;
    float4 pa0, pa1, pb0, pb1;

    // ---- prologue (tile 0) ----
    {
        pa0 = make_float4(0.f,0.f,0.f,0.f); pa1 = pa0; pb0 = pa0; pb1 = pa0;
        if (MODE == 0) {
            bool v = mval && ((unsigned)(y - 1) < (unsigned)Himg) &&
                     ((unsigned)(x - 1) < (unsigned)Himg);
            if (v) {
                const float* src = A + (((size_t)nImg * Himg + (y - 1)) * Himg + (x - 1)) * Cin + kq;
                pa0 = *(const float4*)src;
                pa1 = *(const float4*)(src + 4);
            }
        } else if (mval) {
            const float* src = A + (size_t)gm * K + kq;
            pa0 = *(const float4*)src;
            pa1 = *(const float4*)(src + 4);
        }
        const float* s0 = Bw + (size_t)bk * N + gn;
        const float* s1 = Bw + (size_t)(bk + 8) * N + gn;
        if (VECB) {
            if (gn < N) { pb0 = *(const float4*)s0; pb1 = *(const float4*)s1; }
        } else {
            if (gn + 3 < N) { pb0.x=s0[0]; pb0.y=s0[1]; pb0.z=s0[2]; pb0.w=s0[3];
                              pb1.x=s1[0]; pb1.y=s1[1]; pb1.z=s1[2]; pb1.w=s1[3]; }
            else { if (gn < N) { pb0.x=s0[0]; pb1.x=s1[0]; }
                   if (gn+1 < N) { pb0.y=s0[1]; pb1.y=s1[1]; }
                   if (gn+2 < N) { pb0.z=s0[2]; pb1.z=s1[2]; } }
        }
    }
    #pragma unroll
    for (int q = 0; q < 4; q++) As[0][kq + q][am] = ((const float*)&pa0)[q];
    #pragma unroll
    for (int q = 0; q < 4; q++) As[0][kq + 4 + q][am] = ((const float*)&pa1)[q];
    *(float4*)&Bs[0][bk][bn0] = pb0;
    *(float4*)&Bs[0][bk + 8][bn0] = pb1;
    __syncthreads();

    int cur = 0;
    for (int kt = 0; kt < nt; kt++) {
        const bool more = (kt + 1) < nt;
        if (more) {
            const int k0 = (kt + 1) << 4;
            pa0 = make_float4(0.f,0.f,0.f,0.f); pa1 = pa0; pb0 = pa0; pb1 = pa0;
            if (MODE == 0) {
                int win = k0 >> cshift;
                int ky = win / 3, kx = win - ky * 3;
                int yy = y + ky - 1, xx = x + kx - 1;
                bool v = mval && ((unsigned)yy < (unsigned)Himg) && ((unsigned)xx < (unsigned)Himg);
                if (v) {
                    const float* src = A + (((size_t)nImg * Himg + yy) * Himg + xx) * Cin
                                         + (k0 & (Cin - 1)) + kq;
                    pa0 = *(const float4*)src;
                    pa1 = *(const float4*)(src + 4);
                }
            } else if (mval) {
                const float* src = A + (size_t)gm * K + k0 + kq;
                pa0 = *(const float4*)src;
                pa1 = *(const float4*)(src + 4);
            }
            const float* s0 = Bw + (size_t)(k0 + bk) * N + gn;
            const float* s1 = Bw + (size_t)(k0 + bk + 8) * N + gn;
            if (VECB) {
                if (gn < N) { pb0 = *(const float4*)s0; pb1 = *(const float4*)s1; }
            } else {
                if (gn + 3 < N) { pb0.x=s0[0]; pb0.y=s0[1]; pb0.z=s0[2]; pb0.w=s0[3];
                                  pb1.x=s1[0]; pb1.y=s1[1]; pb1.z=s1[2]; pb1.w=s1[3]; }
                else { if (gn < N) { pb0.x=s0[0]; pb1.x=s1[0]; }
                       if (gn+1 < N) { pb0.y=s0[1]; pb1.y=s1[1]; }
                       if (gn+2 < N) { pb0.z=s0[2]; pb1.z=s1[2]; } }
            }
        }
        #pragma unroll
        for (int kk = 0; kk < 16; kk++) {
            float4 a0 = *(const float4*)&As[cur][kk][ty * 8];
            float4 a1 = *(const float4*)&As[cur][kk][ty * 8 + 4];
            float4 b0 = *(const float4*)&Bs[cur][kk][tx * 8];
            float4 b1 = *(const float4*)&Bs[cur][kk][tx * 8 + 4];
            float av[8] = {a0.x, a0.y, a0.z, a0.w, a1.x, a1.y, a1.z, a1.w};
            float bv[8] = {b0.x, b0.y, b0.z, b0.w, b1.x, b1.y, b1.z, b1.w};
            #pragma unroll
            for (int i = 0; i < 8; i++)
                #pragma unroll
                for (int j = 0; j < 8; j++)
                    acc[i][j] = fmaf(av[i], bv[j], acc[i][j]);
        }
        if (more) {
            int nb = cur ^ 1;
            #pragma unroll
            for (int q = 0; q < 4; q++) As[nb][kq + q][am] = ((const float*)&pa0)[q];
            #pragma unroll
            for (int q = 0; q < 4; q++) As[nb][kq + 4 + q][am] = ((const float*)&pa1)[q];
            *(float4*)&Bs[nb][bk][bn0] = pb0;
            *(float4*)&Bs[nb][bk + 8][bn0] = pb1;
            __syncthreads();
            cur = nb;
        }
    }

    if (MODE == 0) {
        float gg[8], bb[8];
        #pragma unroll
        for (int j = 0; j < 8; j++) {
            int nn = bn + tx * 8 + j;
            gg[j] = p0[nn]; bb[j] = p1[nn];
        }
        #pragma unroll
        for (int i = 0; i < 8; i++) {
            int mm = m0 + ty * 8 + i;
            if (mm >= M) continue;
            float* o = out + (size_t)mm * N + bn + tx * 8;
            float4 v0, v1;
            float w0 = fmaf(acc[i][0], gg[0], bb[0]); v0.x = w0 > 0.f ? w0 : 0.1f * w0;
            float w1 = fmaf(acc[i][1], gg[1], bb[1]); v0.y = w1 > 0.f ? w1 : 0.1f * w1;
            float w2 = fmaf(acc[i][2], gg[2], bb[2]); v0.z = w2 > 0.f ? w2 : 0.1f * w2;
            float w3 = fmaf(acc[i][3], gg[3], bb[3]); v0.w = w3 > 0.f ? w3 : 0.1f * w3;
            float w4 = fmaf(acc[i][4], gg[4], bb[4]); v1.x = w4 > 0.f ? w4 : 0.1f * w4;
            float w5 = fmaf(acc[i][5], gg[5], bb[5]); v1.y = w5 > 0.f ? w5 : 0.1f * w5;
            float w6 = fmaf(acc[i][6], gg[6], bb[6]); v1.z = w6 > 0.f ? w6 : 0.1f * w6;
            float w7 = fmaf(acc[i][7], gg[7], bb[7]); v1.w = w7 > 0.f ? w7 : 0.1f * w7;
            *(float4*)o = v0;
            *(float4*)(o + 4) = v1;
        }
    } else {
        #pragma unroll
        for (int i = 0; i < 8; i++) {
            int mm = m0 + ty * 8 + i;
            if (mm >= M) continue;
            #pragma unroll
            for (int j = 0; j < 8; j++) {
                int nn = bn + tx * 8 + j;
                if (nn < N) out[(size_t)mm * N + nn] = acc[i][j] + p1[nn];
            }
        }
    }
}

__global__ void decode_kernel(const float* __restrict__ pred, int Hl, int lvloff,
                              int abase, float stride)
{
    int idx = blockIdx.x * blockDim.x + threadIdx.x;
    int total = BB * Hl * Hl * 3;
    if (idx >= total) return;
    int a = idx % 3;
    int r = idx / 3;
    int hw = Hl * Hl;
    int b = r / hw;
    int cell = r - b * hw;
    int y = cell / Hl, x = cell - y * Hl;
    const float* p = pred + (size_t)r * 255 + a * 85;
    float cx = (fmaf(sigmoid_f(p[0]), 1.05f, -0.025f) + (float)x) * stride;
    float cy = (fmaf(sigmoid_f(p[1]), 1.05f, -0.025f) + (float)y) * stride;
    float w = exp_f(p[2]) * c_anch[abase + a][0];
    float h = exp_f(p[3]) * c_anch[abase + a][1];
    int g = lvloff + cell * 3 + a;
    float* bx = g_boxes + ((size_t)b * ANCH + g) * 4;
    bx[0] = cx - 0.5f * w; bx[1] = cy - 0.5f * h;
    bx[2] = cx + 0.5f * w; bx[3] = cy + 0.5f * h;
    float sobj = sigmoid_f(p[4]);
    float* sc = g_scores + ((size_t)b * ANCH + g) * 80;
    #pragma unroll 4
    for (int c = 0; c < 80; c++) sc[c] = sobj * sigmoid_f(p[5 + c]);
}

__global__ void zero_kernel() {
    int i = blockIdx.x * blockDim.x + threadIdx.x;
    if (i < BB * 65536) g_h16[i] = 0u;
    if (i < BB) { g_candn[i] = 0; g_p16[i] = 0u; }
}

// 16-bit-prefix histogram; smem ushort-pair counters (128KB dynamic).
// grid (32, BB): per-block item count 56858 < 65536 -> no ushort overflow.
__global__ void __launch_bounds__(256) hist16_kernel() {
    extern __shared__ unsigned shw[];          // 32768 words = 65536 ushort bins
    const int b = blockIdx.y;
    for (int i = threadIdx.x; i < 32768; i += 256) shw[i] = 0u;
    __syncthreads();
    const float* s = g_scores + (size_t)b * (ANCH * 80);
    const int n = ANCH * 80;
    const int stride = 256 * gridDim.x;
    for (int i = blockIdx.x * 256 + threadIdx.x; i < n; i += stride) {
        float v = s[i];
        if (v >= 0.05f) {
            unsigned bin = __float_as_uint(v) >> 16;
            unsigned act = __activemask();
            unsigned mm = __match_any_sync(act, bin);
            if ((threadIdx.x & 31) == __ffs(mm) - 1)
                atomicAdd(&shw[bin >> 1], (unsigned)__popc(mm) << ((bin & 1) * 16));
        }
    }
    __syncthreads();
    for (int i = threadIdx.x; i < 32768; i += 256) {
        unsigned w = shw[i];
        if (w) {
            unsigned lo = w & 0xFFFFu, hi = w >> 16;
            if (lo) atomicAdd(&g_h16[b * 65536 + 2 * i], lo);
            if (hi) atomicAdd(&g_h16[b * 65536 + 2 * i + 1], hi);
        }
    }
}

__global__ void select16_kernel() {
    __shared__ unsigned part[256];
    const int b = blockIdx.x, t = threadIdx.x;
    const unsigned* h = g_h16 + b * 65536;
    const int hi = 65536 - 256 * t;
    const int lo = hi - 256;
    unsigned sum = 0;
    for (int i = lo; i < hi; i++) sum += h[i];
    part[t] = sum;
    __syncthreads();
    unsigned pre = 0;
    for (int i = 0; i < t; i++) pre += part[i];
    if (pre < PRE) {
        unsigned cum = pre;
        for (int i = hi - 1; i >= lo; i--) {
            unsigned c = h[i];
            if (cum < PRE && cum + c >= PRE) g_p16[b] = (unsigned)i;
            cum += c;
        }
    }
}

__global__ void compact_kernel() {
    const int b = blockIdx.y;
    const unsigned p16 = g_p16[b];
    const float* s = g_scores + (size_t)b * (ANCH * 80);
    const int n = ANCH * 80;
    const int stride = blockDim.x * gridDim.x;
    for (int i = blockIdx.x * blockDim.x + threadIdx.x; i < n; i += stride) {
        float v = s[i];
        if (v >= 0.05f) {
            unsigned bits = __float_as_uint(v);
            if ((bits >> 16) >= p16) {
                int pos = atomicAdd(&g_candn[b], 1);
                if (pos < NCAND)
                    g_ckey[b * NCAND + pos] =
                        ((unsigned long long)(~bits) << 32) | (unsigned)i;
            }
        }
    }
}

__device__ void bitonic(unsigned long long* keys, int n) {
    const int t = threadIdx.x, nt = blockDim.x;
    for (int k = 2; k <= n; k <<= 1)
        for (int j = k >> 1; j > 0; j >>= 1) {
            for (int i = t; i < n; i += nt) {
                int ixj = i ^ j;
                if (ixj > i) {
                    unsigned long long a = keys[i], c = keys[ixj];
                    bool sw = ((i & k) == 0) ? (a > c) : (a < c);
                    if (sw) { keys[i] = c; keys[ixj] = a; }
                }
            }
            __syncthreads();
        }
}

__global__ void __launch_bounds__(256) sortcand_kernel() {
    __shared__ unsigned long long keys[NCAND];
    const int b = blockIdx.x, t = threadIdx.x;
    int n = g_candn[b]; if (n > NCAND) n = NCAND;
    for (int i = t; i < NCAND; i += blockDim.x)
        keys[i] = (i < n) ? g_ckey[b * NCAND + i] : 0xFFFFFFFFFFFFFFFFull;
    __syncthreads();
    bitonic(keys, NCAND);
    for (int i = t; i < PRE; i += blockDim.x) {
        if (i < n) {
            unsigned long long k = keys[i];
            g_topi[b * PRE + i] = (int)(unsigned)(k & 0xffffffffu);
            g_tops[b * PRE + i] = __uint_as_float(~(unsigned)(k >> 32));
        } else {
            g_topi[b * PRE + i] = 0;
            g_tops[b * PRE + i] = 0.f;
        }
    }
}

__global__ void __launch_bounds__(256) nms_kernel(float* __restrict__ dout) {
    __shared__ float x1s[PRE], y1s[PRE], x2s[PRE], y2s[PRE];
    __shared__ float rbx[PRE][4];
    __shared__ float ar[PRE], sc[PRE];
    __shared__ int cls[PRE];
    __shared__ unsigned sup[PRE][13];
    __shared__ unsigned keepw[13];
    __shared__ unsigned long long keys[512];
    const int b = blockIdx.x, t = threadIdx.x;
    for (int i = t; i < PRE; i += 256) {
        float s = g_tops[b * PRE + i];
        int fi = g_topi[b * PRE + i];
        int aidx = fi / 80;
        int c = fi - aidx * 80;
        const float* bx = g_boxes + ((size_t)b * ANCH + aidx) * 4;
        float off = (float)c * 1216.0f;
        float X1 = bx[0], Y1 = bx[1], X2 = bx[2], Y2 = bx[3];
        rbx[i][0] = X1; rbx[i][1] = Y1; rbx[i][2] = X2; rbx[i][3] = Y2;
        x1s[i] = X1 + off; y1s[i] = Y1 + off;
        x2s[i] = X2 + off; y2s[i] = Y2 + off;
        ar[i] = (X2 - X1) * (Y2 - Y1);
        sc[i] = s; cls[i] = c;
    }
    if (t < 13) keepw[t] = 0xFFFFFFFFu;
    __syncthreads();
    for (int i = t; i < PRE; i += 256) {
        float ax1 = x1s[i], ay1 = y1s[i], ax2 = x2s[i], ay2 = y2s[i], aa = ar[i];
        unsigned row[13];
        #pragma unroll
        for (int w = 0; w < 13; w++) row[w] = 0u;
        for (int j = i + 1; j < PRE; j++) {
            float ltx = fmaxf(ax1, x1s[j]), lty = fmaxf(ay1, y1s[j]);
            float rbxv = fminf(ax2, x2s[j]), rby = fminf(ay2, y2s[j]);
            float iw = fmaxf(rbxv - ltx, 0.f), ih = fmaxf(rby - lty, 0.f);
            float inter = iw * ih;
            float iou = fdiv_rn(inter, aa + ar[j] - inter + 1e-7f);
            if (iou > 0.5f) row[j >> 5] |= 1u << (j & 31);
        }
        #pragma unroll
        for (int w = 0; w < 13; w++) sup[i][w] = row[w];
    }
    __syncthreads();
    if (t == 0) {
        for (int i = 0; i < PRE; i++)
            if (((keepw[i >> 5] >> (i & 31)) & 1u) && sc[i] > 0.f)
                for (int w = i >> 5; w < 13; w++) keepw[w] &= ~sup[i][w];
    }
    __syncthreads();
    for (int i = t; i < 512; i += 256) {
        if (i < PRE) {
            bool k = (keepw[i >> 5] >> (i & 31)) & 1u;
            float fs = k ? sc[i] : 0.f;
            keys[i] = ((unsigned long long)(~__float_as_uint(fs)) << 32) | (unsigned)i;
        } else keys[i] = 0xFFFFFFFFFFFFFFFFull;
    }
    __syncthreads();
    bitonic(keys, 512);
    for (int k = t; k < 100; k += 256) {
        unsigned long long key = keys[k];
        unsigned idx = (unsigned)(key & 0xffffffffu);
        float s = __uint_as_float(~(unsigned)(key >> 32));
        float o0 = 0, o1 = 0, o2 = 0, o3 = 0, cf = 0;
        if (idx < PRE) {
            o0 = rbx[idx][0]; o1 = rbx[idx][1]; o2 = rbx[idx][2]; o3 = rbx[idx][3];
            cf = (float)cls[idx];
        } else s = 0.f;
        float* ob = dout + ((size_t)b * 100 + k) * 4;
        ob[0] = o0; ob[1] = o1; ob[2] = o2; ob[3] = o3;
        dout[3200 + b * 100 + k] = s;
        dout[4000 + b * 100 + k] = cf;
    }
}

extern "C" void kernel_launch(void* const* d_in, const int* in_sizes, int n_in,
                              void* d_out, int out_size) {
    const float *f[3], *w3[3], *ga[3], *be[3], *w1[3], *b1[3];
    bool sig = (in_sizes[1] == 2957312);  // f1 in signature order
    for (int i = 0; i < 3; i++) {
        if (sig) {
            f[i]  = (const float*)d_in[i];
            w3[i] = (const float*)d_in[3 + 5 * i];
            ga[i] = (const float*)d_in[4 + 5 * i];
            be[i] = (const float*)d_in[5 + 5 * i];
            w1[i] = (const float*)d_in[6 + 5 * i];
            b1[i] = (const float*)d_in[7 + 5 * i];
        } else {
            int o = 6 * i;
            f[i]  = (const float*)d_in[o];
            w3[i] = (const float*)d_in[o + 1];
            ga[i] = (const float*)d_in[o + 2];
            be[i] = (const float*)d_in[o + 3];
            w1[i] = (const float*)d_in[o + 4];
            b1[i] = (const float*)d_in[o + 5];
        }
    }
    float *px = nullptr, *ppred = nullptr;
    cudaGetSymbolAddress((void**)&px, g_x);
    cudaGetSymbolAddress((void**)&ppred, g_pred);
    cudaFuncSetAttribute(hist16_kernel, cudaFuncAttributeMaxDynamicSharedMemorySize, 131072);

    static const int   Hs[3]    = {76, 38, 19};
    static const int   Cins[3]  = {128, 256, 512};
    static const int   CSH[3]   = {7, 8, 9};
    static const int   HDs[3]   = {256, 512, 1024};
    static const int   LOFF[3]  = {0, 17328, 21660};
    static const int   ABASE[3] = {0, 3, 6};
    static const float STR[3]   = {8.f, 16.f, 32.f};

    zero_kernel<<<(BB * 65536 + 255) / 256, 256>>>();

    for (int i = 0; i < 3; i++) {
        int H = Hs[i], Cin = Cins[i], hd = HDs[i];
        int M = BB * H * H;
        dim3 g1(hd / 128, (M + 127) / 128);
        gemm2_kernel<0, 1><<<g1, 256>>>(f[i], w3[i], ga[i], be[i], px,
                                        M, hd, 9 * Cin, H, Cin, CSH[i]);
        dim3 g2(2, (M + 127) / 128);
        gemm2_kernel<1, 0><<<g2, 256>>>(px, w1[i], b1[i], b1[i], ppred,
                                        M, 255, hd, 0, 0, 0);
        int tot = M * 3;
        decode_kernel<<<(tot + 255) / 256, 256>>>(ppred, H, LOFF[i], ABASE[i], STR[i]);
    }

    dim3 hg(32, BB);
    hist16_kernel<<<hg, 256, 131072>>>();
    select16_kernel<<<BB, 256>>>();
    compact_kernel<<<hg, 256>>>();
    sortcand_kernel<<<BB, 256>>>();
    nms_kernel<<<BB, 256>>>((float*)d_out);
}

// round 10
// speedup vs baseline: 1.2169x; 1.1130x over previous
#include <cuda_runtime.h>
#include <cstdint>

#define BB 8
#define ANCH 22743
#define PRE 400
#define NCAND 4096

static __device__ float g_x[20700672];     // per-level offsets {0, 11829248, 17743872}
static __device__ float g_pred[15465240];  // per-level offsets {0, 11783040, 14728800}
static __device__ float g_boxes[BB * ANCH * 4];
static __device__ float g_scores[BB * ANCH * 80];
static __device__ unsigned g_h16[BB * 65536];
static __device__ unsigned g_p16[BB];
static __device__ int g_candn[BB];
static __device__ unsigned long long g_ckey[BB * NCAND];
static __device__ float g_tops[BB * PRE];
static __device__ int g_topi[BB * PRE];

__constant__ float c_anch[9][2] = {{12,16},{19,36},{40,28},{36,75},{76,55},
                                   {72,146},{142,110},{192,243},{459,401}};

__device__ __forceinline__ float fdiv_rn(float a, float b) {
    float r; asm("div.rn.f32 %0,%1,%2;" : "=f"(r) : "f"(a), "f"(b)); return r;
}
__device__ __forceinline__ float exp_f(float x) {
    float n = rintf(x * 1.4426950408889634f);
    float r = fmaf(n, -0.693359375f, x);
    r = fmaf(n, 2.12194440e-4f, r);
    float p = 1.98412698e-4f;
    p = fmaf(p, r, 1.38888889e-3f);
    p = fmaf(p, r, 8.33333333e-3f);
    p = fmaf(p, r, 4.16666667e-2f);
    p = fmaf(p, r, 0.166666667f);
    p = fmaf(p, r, 0.5f);
    p = fmaf(p, r, 1.0f);
    p = fmaf(p, r, 1.0f);
    int ni = (int)n; ni = ni < -126 ? -126 : (ni > 127 ? 127 : ni);
    return p * __int_as_float((ni + 127) << 23);
}
__device__ __forceinline__ float sigmoid_f(float x) {
    return fdiv_rn(1.0f, 1.0f + exp_f(-x));
}

// ---- fused 3x3 implicit-GEMM conv + BN + leaky; all 3 levels in one launch ----
// tiles: L0 361m x 2n = 722, L1 91 x 4 = 364, L2 23 x 8 = 184; total 1270
__global__ void __launch_bounds__(256) conv3_fused(
    const float* __restrict__ f0, const float* __restrict__ f1, const float* __restrict__ f2,
    const float* __restrict__ w0, const float* __restrict__ w1w, const float* __restrict__ w2,
    const float* __restrict__ ga0, const float* __restrict__ ga1, const float* __restrict__ ga2,
    const float* __restrict__ be0, const float* __restrict__ be1, const float* __restrict__ be2)
{
    __shared__ __align__(16) float As[2][16][132];
    __shared__ __align__(16) float Bs[2][16][132];
    const int bid = blockIdx.x;
    int M, N, K, Himg, Cin, csh, MT, loc;
    size_t xoff;
    const float *A, *Bw, *p0, *p1;
    if (bid < 722) {
        M = 46208; N = 256; K = 1152; Himg = 76; Cin = 128; csh = 7; MT = 361;
        xoff = 0; A = f0; Bw = w0; p0 = ga0; p1 = be0; loc = bid;
    } else if (bid < 1086) {
        M = 11552; N = 512; K = 2304; Himg = 38; Cin = 256; csh = 8; MT = 91;
        xoff = 11829248ull; A = f1; Bw = w1w; p0 = ga1; p1 = be1; loc = bid - 722;
    } else {
        M = 2888; N = 1024; K = 4608; Himg = 19; Cin = 512; csh = 9; MT = 23;
        xoff = 17743872ull; A = f2; Bw = w2; p0 = ga2; p1 = be2; loc = bid - 1086;
    }
    float* out = g_x + xoff;
    const int bnIdx = loc / MT, mIdx = loc - bnIdx * MT;
    const int bn = bnIdx << 7, m0 = mIdx << 7;

    const int t = threadIdx.x;
    const int tx = t & 15, ty = t >> 4;
    const int am = t >> 1, kq = (t & 1) * 8;
    const int gm = m0 + am;
    const bool mval = gm < M;
    int nImg = 0, y = 0, x = 0;
    {
        int hw = Himg * Himg;
        int gg = mval ? gm : 0;
        nImg = gg / hw; int rr = gg - nImg * hw; y = rr / Himg; x = rr - y * Himg;
    }
    const int bk = t >> 5, bn0 = (t & 31) * 4;
    const int gn = bn + bn0;

    float acc[8][8];
    #pragma unroll
    for (int i = 0; i < 8; i++)
        #pragma unroll
        for (int j = 0; j < 8; j++) acc[i][j] = 0.f;

    const int nt = K >> 4;
    float4 pa0, pa1, pb0, pb1;
    {
        pa0 = make_float4(0.f,0.f,0.f,0.f); pa1 = pa0;
        bool v = mval && ((unsigned)(y - 1) < (unsigned)Himg) &&
                 ((unsigned)(x - 1) < (unsigned)Himg);
        if (v) {
            const float* src = A + (((size_t)nImg * Himg + (y - 1)) * Himg + (x - 1)) * Cin + kq;
            pa0 = *(const float4*)src; pa1 = *(const float4*)(src + 4);
        }
        pb0 = *(const float4*)(Bw + (size_t)bk * N + gn);
        pb1 = *(const float4*)(Bw + (size_t)(bk + 8) * N + gn);
    }
    #pragma unroll
    for (int q = 0; q < 4; q++) As[0][kq + q][am] = ((const float*)&pa0)[q];
    #pragma unroll
    for (int q = 0; q < 4; q++) As[0][kq + 4 + q][am] = ((const float*)&pa1)[q];
    *(float4*)&Bs[0][bk][bn0] = pb0;
    *(float4*)&Bs[0][bk + 8][bn0] = pb1;
    __syncthreads();

    int cur = 0;
    for (int kt = 0; kt < nt; kt++) {
        const bool more = (kt + 1) < nt;
        if (more) {
            const int k0 = (kt + 1) << 4;
            pa0 = make_float4(0.f,0.f,0.f,0.f); pa1 = pa0;
            int win = k0 >> csh;
            int ky = win / 3, kx = win - ky * 3;
            int yy = y + ky - 1, xx = x + kx - 1;
            bool v = mval && ((unsigned)yy < (unsigned)Himg) && ((unsigned)xx < (unsigned)Himg);
            if (v) {
                const float* src = A + (((size_t)nImg * Himg + yy) * Himg + xx) * Cin
                                     + (k0 & (Cin - 1)) + kq;
                pa0 = *(const float4*)src; pa1 = *(const float4*)(src + 4);
            }
            pb0 = *(const float4*)(Bw + (size_t)(k0 + bk) * N + gn);
            pb1 = *(const float4*)(Bw + (size_t)(k0 + bk + 8) * N + gn);
        }
        #pragma unroll
        for (int kk = 0; kk < 16; kk++) {
            float4 a0 = *(const float4*)&As[cur][kk][ty * 8];
            float4 a1 = *(const float4*)&As[cur][kk][ty * 8 + 4];
            float4 b0 = *(const float4*)&Bs[cur][kk][tx * 8];
            float4 b1 = *(const float4*)&Bs[cur][kk][tx * 8 + 4];
            float av[8] = {a0.x, a0.y, a0.z, a0.w, a1.x, a1.y, a1.z, a1.w};
            float bv[8] = {b0.x, b0.y, b0.z, b0.w, b1.x, b1.y, b1.z, b1.w};
            #pragma unroll
            for (int i = 0; i < 8; i++)
                #pragma unroll
                for (int j = 0; j < 8; j++)
                    acc[i][j] = fmaf(av[i], bv[j], acc[i][j]);
        }
        if (more) {
            int nb = cur ^ 1;
            #pragma unroll
            for (int q = 0; q < 4; q++) As[nb][kq + q][am] = ((const float*)&pa0)[q];
            #pragma unroll
            for (int q = 0; q < 4; q++) As[nb][kq + 4 + q][am] = ((const float*)&pa1)[q];
            *(float4*)&Bs[nb][bk][bn0] = pb0;
            *(float4*)&Bs[nb][bk + 8][bn0] = pb1;
            __syncthreads();
            cur = nb;
        }
    }

    float gg[8], bb[8];
    #pragma unroll
    for (int j = 0; j < 8; j++) {
        int nn = bn + tx * 8 + j;
        gg[j] = p0[nn]; bb[j] = p1[nn];
    }
    #pragma unroll
    for (int i = 0; i < 8; i++) {
        int mm = m0 + ty * 8 + i;
        if (mm >= M) continue;
        float* o = out + (size_t)mm * N + bn + tx * 8;
        float4 v0, v1;
        float w0_ = fmaf(acc[i][0], gg[0], bb[0]); v0.x = w0_ > 0.f ? w0_ : 0.1f * w0_;
        float w1_ = fmaf(acc[i][1], gg[1], bb[1]); v0.y = w1_ > 0.f ? w1_ : 0.1f * w1_;
        float w2_ = fmaf(acc[i][2], gg[2], bb[2]); v0.z = w2_ > 0.f ? w2_ : 0.1f * w2_;
        float w3_ = fmaf(acc[i][3], gg[3], bb[3]); v0.w = w3_ > 0.f ? w3_ : 0.1f * w3_;
        float w4_ = fmaf(acc[i][4], gg[4], bb[4]); v1.x = w4_ > 0.f ? w4_ : 0.1f * w4_;
        float w5_ = fmaf(acc[i][5], gg[5], bb[5]); v1.y = w5_ > 0.f ? w5_ : 0.1f * w5_;
        float w6_ = fmaf(acc[i][6], gg[6], bb[6]); v1.z = w6_ > 0.f ? w6_ : 0.1f * w6_;
        float w7_ = fmaf(acc[i][7], gg[7], bb[7]); v1.w = w7_ > 0.f ? w7_ : 0.1f * w7_;
        *(float4*)o = v0;
        *(float4*)(o + 4) = v1;
    }
}

// ---- fused 1x1 conv + bias (N=255); tiles: 722 + 182 + 46 = 950 ----
__global__ void __launch_bounds__(256) gemm1x1_fused(
    const float* __restrict__ wa, const float* __restrict__ wb, const float* __restrict__ wc,
    const float* __restrict__ ba, const float* __restrict__ bbv, const float* __restrict__ bc)
{
    __shared__ __align__(16) float As[2][16][132];
    __shared__ __align__(16) float Bs[2][16][132];
    const int bid = blockIdx.x;
    int M, K, loc;
    size_t xoff, poff;
    const float *Bw, *p1;
    if (bid < 722) {
        M = 46208; K = 256; xoff = 0; poff = 0; Bw = wa; p1 = ba; loc = bid;
    } else if (bid < 904) {
        M = 11552; K = 512; xoff = 11829248ull; poff = 11783040ull; Bw = wb; p1 = bbv; loc = bid - 722;
    } else {
        M = 2888; K = 1024; xoff = 17743872ull; poff = 14728800ull; Bw = wc; p1 = bc; loc = bid - 904;
    }
    const float* A = g_x + xoff;
    float* out = g_pred + poff;
    const int N = 255;
    const int bnIdx = loc & 1, mIdx = loc >> 1;
    const int bn = bnIdx << 7, m0 = mIdx << 7;

    const int t = threadIdx.x;
    const int tx = t & 15, ty = t >> 4;
    const int am = t >> 1, kq = (t & 1) * 8;
    const int gm = m0 + am;
    const bool mval = gm < M;
    const int bk = t >> 5, bn0 = (t & 31) * 4;
    const int gn = bn + bn0;

    float acc[8][8];
    #pragma unroll
    for (int i = 0; i < 8; i++)
        #pragma unroll
        for (int j = 0; j < 8; j++) acc[i][j] = 0.f;

    const int nt = K >> 4;
    float4 pa0, pa1, pb0, pb1;
    {
        pa0 = make_float4(0.f,0.f,0.f,0.f); pa1 = pa0; pb0 = pa0; pb1 = pa0;
        if (mval) {
            const float* src = A + (size_t)gm * K + kq;
            pa0 = *(const float4*)src; pa1 = *(const float4*)(src + 4);
        }
        const float* s0 = Bw + (size_t)bk * N + gn;
        const float* s1 = Bw + (size_t)(bk + 8) * N + gn;
        if (gn + 3 < N) { pb0.x=s0[0]; pb0.y=s0[1]; pb0.z=s0[2]; pb0.w=s0[3];
                          pb1.x=s1[0]; pb1.y=s1[1]; pb1.z=s1[2]; pb1.w=s1[3]; }
        else { if (gn < N) { pb0.x=s0[0]; pb1.x=s1[0]; }
               if (gn+1 < N) { pb0.y=s0[1]; pb1.y=s1[1]; }
               if (gn+2 < N) { pb0.z=s0[2]; pb1.z=s1[2]; } }
    }
    #pragma unroll
    for (int q = 0; q < 4; q++) As[0][kq + q][am] = ((const float*)&pa0)[q];
    #pragma unroll
    for (int q = 0; q < 4; q++) As[0][kq + 4 + q][am] = ((const float*)&pa1)[q];
    *(float4*)&Bs[0][bk][bn0] = pb0;
    *(float4*)&Bs[0][bk + 8][bn0] = pb1;
    __syncthreads();

    int cur = 0;
    for (int kt = 0; kt < nt; kt++) {
        const bool more = (kt + 1) < nt;
        if (more) {
            const int k0 = (kt + 1) << 4;
            pa0 = make_float4(0.f,0.f,0.f,0.f); pa1 = pa0; pb0 = pa0; pb1 = pa0;
            if (mval) {
                const float* src = A + (size_t)gm * K + k0 + kq;
                pa0 = *(const float4*)src; pa1 = *(const float4*)(src + 4);
            }
            const float* s0 = Bw + (size_t)(k0 + bk) * N + gn;
            const float* s1 = Bw + (size_t)(k0 + bk + 8) * N + gn;
            if (gn + 3 < N) { pb0.x=s0[0]; pb0.y=s0[1]; pb0.z=s0[2]; pb0.w=s0[3];
                              pb1.x=s1[0]; pb1.y=s1[1]; pb1.z=s1[2]; pb1.w=s1[3]; }
            else { if (gn < N) { pb0.x=s0[0]; pb1.x=s1[0]; }
                   if (gn+1 < N) { pb0.y=s0[1]; pb1.y=s1[1]; }
                   if (gn+2 < N) { pb0.z=s0[2]; pb1.z=s1[2]; } }
        }
        #pragma unroll
        for (int kk = 0; kk < 16; kk++) {
            float4 a0 = *(const float4*)&As[cur][kk][ty * 8];
            float4 a1 = *(const float4*)&As[cur][kk][ty * 8 + 4];
            float4 b0 = *(const float4*)&Bs[cur][kk][tx * 8];
            float4 b1 = *(const float4*)&Bs[cur][kk][tx * 8 + 4];
            float av[8] = {a0.x, a0.y, a0.z, a0.w, a1.x, a1.y, a1.z, a1.w};
            float bv[8] = {b0.x, b0.y, b0.z, b0.w, b1.x, b1.y, b1.z, b1.w};
            #pragma unroll
            for (int i = 0; i < 8; i++)
                #pragma unroll
                for (int j = 0; j < 8; j++)
                    acc[i][j] = fmaf(av[i], bv[j], acc[i][j]);
        }
        if (more) {
            int nb = cur ^ 1;
            #pragma unroll
            for (int q = 0; q < 4; q++) As[nb][kq + q][am] = ((const float*)&pa0)[q];
            #pragma unroll
            for (int q = 0; q < 4; q++) As[nb][kq + 4 + q][am] = ((const float*)&pa1)[q];
            *(float4*)&Bs[nb][bk][bn0] = pb0;
            *(float4*)&Bs[nb][bk + 8][bn0] = pb1;
            __syncthreads();
            cur = nb;
        }
    }
    #pragma unroll
    for (int i = 0; i < 8; i++) {
        int mm = m0 + ty * 8 + i;
        if (mm >= M) continue;
        #pragma unroll
        for (int j = 0; j < 8; j++) {
            int nn = bn + tx * 8 + j;
            if (nn < N) out[(size_t)mm * N + nn] = acc[i][j] + p1[nn];
        }
    }
}

// ---- fused decode: all 3 levels, 181944 items ----
__global__ void decode_fused() {
    int idx = blockIdx.x * blockDim.x + threadIdx.x;
    if (idx >= 181944) return;
    int l = (idx >= 138624) + (idx >= 173280);
    int Hl, lvloff, abase; float stride; size_t poff; int rel;
    if (l == 0)      { Hl = 76; lvloff = 0;     abase = 0; stride = 8.f;  poff = 0;           rel = idx; }
    else if (l == 1) { Hl = 38; lvloff = 17328; abase = 3; stride = 16.f; poff = 11783040ull; rel = idx - 138624; }
    else             { Hl = 19; lvloff = 21660; abase = 6; stride = 32.f; poff = 14728800ull; rel = idx - 173280; }
    int a = rel % 3;
    int r = rel / 3;
    int hw = Hl * Hl;
    int b = r / hw;
    int cell = r - b * hw;
    int y = cell / Hl, x = cell - y * Hl;
    const float* p = g_pred + poff + (size_t)r * 255 + a * 85;
    float cx = (fmaf(sigmoid_f(p[0]), 1.05f, -0.025f) + (float)x) * stride;
    float cy = (fmaf(sigmoid_f(p[1]), 1.05f, -0.025f) + (float)y) * stride;
    float w = exp_f(p[2]) * c_anch[abase + a][0];
    float h = exp_f(p[3]) * c_anch[abase + a][1];
    int g = lvloff + cell * 3 + a;
    float* bx = g_boxes + ((size_t)b * ANCH + g) * 4;
    bx[0] = cx - 0.5f * w; bx[1] = cy - 0.5f * h;
    bx[2] = cx + 0.5f * w; bx[3] = cy + 0.5f * h;
    float sobj = sigmoid_f(p[4]);
    float* sc = g_scores + ((size_t)b * ANCH + g) * 80;
    #pragma unroll 4
    for (int c = 0; c < 80; c++) sc[c] = sobj * sigmoid_f(p[5 + c]);
}

__global__ void zero_kernel() {
    int i = blockIdx.x * blockDim.x + threadIdx.x;
    if (i < BB * 65536) g_h16[i] = 0u;
    if (i < BB) { g_candn[i] = 0; g_p16[i] = 0u; }
}

__global__ void __launch_bounds__(256) hist16_kernel() {
    extern __shared__ unsigned shw[];
    const int b = blockIdx.y;
    for (int i = threadIdx.x; i < 32768; i += 256) shw[i] = 0u;
    __syncthreads();
    const float* s = g_scores + (size_t)b * (ANCH * 80);
    const int n = ANCH * 80;
    const int stride = 256 * gridDim.x;
    for (int i = blockIdx.x * 256 + threadIdx.x; i < n; i += stride) {
        float v = s[i];
        if (v >= 0.05f) {
            unsigned bin = __float_as_uint(v) >> 16;
            unsigned act = __activemask();
            unsigned mm = __match_any_sync(act, bin);
            if ((threadIdx.x & 31) == __ffs(mm) - 1)
                atomicAdd(&shw[bin >> 1], (unsigned)__popc(mm) << ((bin & 1) * 16));
        }
    }
    __syncthreads();
    for (int i = threadIdx.x; i < 32768; i += 256) {
        unsigned w = shw[i];
        if (w) {
            unsigned lo = w & 0xFFFFu, hi = w >> 16;
            if (lo) atomicAdd(&g_h16[b * 65536 + 2 * i], lo);
            if (hi) atomicAdd(&g_h16[b * 65536 + 2 * i + 1], hi);
        }
    }
}

__global__ void select16_kernel() {
    __shared__ unsigned part[256];
    const int b = blockIdx.x, t = threadIdx.x;
    const unsigned* h = g_h16 + b * 65536;
    const int hi = 65536 - 256 * t;
    const int lo = hi - 256;
    unsigned sum = 0;
    for (int i = lo; i < hi; i++) sum += h[i];
    part[t] = sum;
    __syncthreads();
    unsigned pre = 0;
    for (int i = 0; i < t; i++) pre += part[i];
    if (pre < PRE) {
        unsigned cum = pre;
        for (int i = hi - 1; i >= lo; i--) {
            unsigned c = h[i];
            if (cum < PRE && cum + c >= PRE) g_p16[b] = (unsigned)i;
            cum += c;
        }
    }
}

__global__ void compact_kernel() {
    const int b = blockIdx.y;
    const unsigned p16 = g_p16[b];
    const float* s = g_scores + (size_t)b * (ANCH * 80);
    const int n = ANCH * 80;
    const int stride = blockDim.x * gridDim.x;
    for (int i = blockIdx.x * blockDim.x + threadIdx.x; i < n; i += stride) {
        float v = s[i];
        if (v >= 0.05f) {
            unsigned bits = __float_as_uint(v);
            if ((bits >> 16) >= p16) {
                int pos = atomicAdd(&g_candn[b], 1);
                if (pos < NCAND)
                    g_ckey[b * NCAND + pos] =
                        ((unsigned long long)(~bits) << 32) | (unsigned)i;
            }
        }
    }
}

__device__ void bitonic(unsigned long long* keys, int n) {
    const int t = threadIdx.x, nt = blockDim.x;
    for (int k = 2; k <= n; k <<= 1)
        for (int j = k >> 1; j > 0; j >>= 1) {
            for (int i = t; i < n; i += nt) {
                int ixj = i ^ j;
                if (ixj > i) {
                    unsigned long long a = keys[i], c = keys[ixj];
                    bool sw = ((i & k) == 0) ? (a > c) : (a < c);
                    if (sw) { keys[i] = c; keys[ixj] = a; }
                }
            }
            __syncthreads();
        }
}

__global__ void __launch_bounds__(256) sortcand_kernel() {
    __shared__ unsigned long long keys[NCAND];
    const int b = blockIdx.x, t = threadIdx.x;
    int n = g_candn[b]; if (n > NCAND) n = NCAND;
    for (int i = t; i < NCAND; i += blockDim.x)
        keys[i] = (i < n) ? g_ckey[b * NCAND + i] : 0xFFFFFFFFFFFFFFFFull;
    __syncthreads();
    bitonic(keys, NCAND);
    for (int i = t; i < PRE; i += blockDim.x) {
        if (i < n) {
            unsigned long long k = keys[i];
            g_topi[b * PRE + i] = (int)(unsigned)(k & 0xffffffffu);
            g_tops[b * PRE + i] = __uint_as_float(~(unsigned)(k >> 32));
        } else {
            g_topi[b * PRE + i] = 0;
            g_tops[b * PRE + i] = 0.f;
        }
    }
}

__global__ void __launch_bounds__(256) nms_kernel(float* __restrict__ dout) {
    __shared__ float x1s[PRE], y1s[PRE], x2s[PRE], y2s[PRE];
    __shared__ float rbx[PRE][4];
    __shared__ float ar[PRE], sc[PRE];
    __shared__ int cls[PRE];
    __shared__ unsigned sup[PRE][13];
    __shared__ unsigned keepw[13];
    __shared__ unsigned long long keys[512];
    const int b = blockIdx.x, t = threadIdx.x;
    for (int i = t; i < PRE; i += 256) {
        float s = g_tops[b * PRE + i];
        int fi = g_topi[b * PRE + i];
        int aidx = fi / 80;
        int c = fi - aidx * 80;
        const float* bx = g_boxes + ((size_t)b * ANCH + aidx) * 4;
        float off = (float)c * 1216.0f;
        float X1 = bx[0], Y1 = bx[1], X2 = bx[2], Y2 = bx[3];
        rbx[i][0] = X1; rbx[i][1] = Y1; rbx[i][2] = X2; rbx[i][3] = Y2;
        x1s[i] = X1 + off; y1s[i] = Y1 + off;
        x2s[i] = X2 + off; y2s[i] = Y2 + off;
        ar[i] = (X2 - X1) * (Y2 - Y1);
        sc[i] = s; cls[i] = c;
    }
    if (t < 13) keepw[t] = 0xFFFFFFFFu;
    __syncthreads();
    for (int i = t; i < PRE; i += 256) {
        float ax1 = x1s[i], ay1 = y1s[i], ax2 = x2s[i], ay2 = y2s[i], aa = ar[i];
        unsigned row[13];
        #pragma unroll
        for (int w = 0; w < 13; w++) row[w] = 0u;
        for (int j = i + 1; j < PRE; j++) {
            float ltx = fmaxf(ax1, x1s[j]), lty = fmaxf(ay1, y1s[j]);
            float rbxv = fminf(ax2, x2s[j]), rby = fminf(ay2, y2s[j]);
            float iw = fmaxf(rbxv - ltx, 0.f), ih = fmaxf(rby - lty, 0.f);
            float inter = iw * ih;
            float iou = fdiv_rn(inter, aa + ar[j] - inter + 1e-7f);
            if (iou > 0.5f) row[j >> 5] |= 1u << (j & 31);
        }
        #pragma unroll
        for (int w = 0; w < 13; w++) sup[i][w] = row[w];
    }
    __syncthreads();
    if (t == 0) {
        for (int i = 0; i < PRE; i++)
            if (((keepw[i >> 5] >> (i & 31)) & 1u) && sc[i] > 0.f)
                for (int w = i >> 5; w < 13; w++) keepw[w] &= ~sup[i][w];
    }
    __syncthreads();
    for (int i = t; i < 512; i += 256) {
        if (i < PRE) {
            bool k = (keepw[i >> 5] >> (i & 31)) & 1u;
            float fs = k ? sc[i] : 0.f;
            keys[i] = ((unsigned long long)(~__float_as_uint(fs)) << 32) | (unsigned)i;
        } else keys[i] = 0xFFFFFFFFFFFFFFFFull;
    }
    __syncthreads();
    bitonic(keys, 512);
    for (int k = t; k < 100; k += 256) {
        unsigned long long key = keys[k];
        unsigned idx = (unsigned)(key & 0xffffffffu);
        float s = __uint_as_float(~(unsigned)(key >> 32));
        float o0 = 0, o1 = 0, o2 = 0, o3 = 0, cf = 0;
        if (idx < PRE) {
            o0 = rbx[idx][0]; o1 = rbx[idx][1]; o2 = rbx[idx][2]; o3 = rbx[idx][3];
            cf = (float)cls[idx];
        } else s = 0.f;
        float* ob = dout + ((size_t)b * 100 + k) * 4;
        ob[0] = o0; ob[1] = o1; ob[2] = o2; ob[3] = o3;
        dout[3200 + b * 100 + k] = s;
        dout[4000 + b * 100 + k] = cf;
    }
}

extern "C" void kernel_launch(void* const* d_in, const int* in_sizes, int n_in,
                              void* d_out, int out_size) {
    const float *f[3], *w3[3], *ga[3], *be[3], *w1[3], *b1[3];
    bool sig = (in_sizes[1] == 2957312);
    for (int i = 0; i < 3; i++) {
        if (sig) {
            f[i]  = (const float*)d_in[i];
            w3[i] = (const float*)d_in[3 + 5 * i];
            ga[i] = (const float*)d_in[4 + 5 * i];
            be[i] = (const float*)d_in[5 + 5 * i];
            w1[i] = (const float*)d_in[6 + 5 * i];
            b1[i] = (const float*)d_in[7 + 5 * i];
        } else {
            int o = 6 * i;
            f[i]  = (const float*)d_in[o];
            w3[i] = (const float*)d_in[o + 1];
            ga[i] = (const float*)d_in[o + 2];
            be[i] = (const float*)d_in[o + 3];
            w1[i] = (const float*)d_in[o + 4];
            b1[i] = (const float*)d_in[o + 5];
        }
    }
    cudaFuncSetAttribute(hist16_kernel, cudaFuncAttributeMaxDynamicSharedMemorySize, 131072);

    zero_kernel<<<(BB * 65536 + 255) / 256, 256>>>();
    conv3_fused<<<1270, 256>>>(f[0], f[1], f[2], w3[0], w3[1], w3[2],
                               ga[0], ga[1], ga[2], be[0], be[1], be[2]);
    gemm1x1_fused<<<950, 256>>>(w1[0], w1[1], w1[2], b1[0], b1[1], b1[2]);
    decode_fused<<<(181944 + 255) / 256, 256>>>();

    dim3 hg(32, BB);
    hist16_kernel<<<hg, 256, 131072>>>();
    select16_kernel<<<BB, 256>>>();
    compact_kernel<<<hg, 256>>>();
    sortcand_kernel<<<BB, 256>>>();
    nms_kernel<<<BB, 256>>>((float*)d_out);
}